// round 1
// baseline (speedup 1.0000x reference)
#include <cuda_runtime.h>

#define BATCH_MAX 16384
#define XDIM 64
#define ADIM 16
#define NCON 8
#define N_ITERS 250
#define POW_ITERS 128
#define EPSC 0.05f   /* 1/(2*PEN) */

// ---------------- scratch (static device globals; no runtime alloc) ----------------
__device__ float g_Y [BATCH_MAX * 512];   // Qc_m x  (flattened r = m*64+i)
__device__ float g_S [BATCH_MAX * 64];    // S = 0.5 Lg Lg^T  (8x8)
__device__ float g_q [BATCH_MAX * 16];    // dual linear term (bottom half zeros)
__device__ float g_Lg[BATCH_MAX * 128];   // Lg_h (8x16)

// =====================================================================
// Kernel 1: Y[b][r] = sum_k X[b][k] * W[r][k],  W = Qc flattened [512][64]
// Tiled SGEMM, M=batch, N=512, K=64.  Block 256 threads, 64x64 tile.
// =====================================================================
__global__ __launch_bounds__(256) void k1_gemm(const float* __restrict__ X,
                                               const float* __restrict__ W)
{
    __shared__ float As[64][72];   // [m][k] padded
    __shared__ float Bs[64][72];   // [k][n] padded (transposed on load)
    const int tid = threadIdx.x;
    const int m0 = blockIdx.y * 64;
    const int n0 = blockIdx.x * 64;

    {
        int row = tid & 63;
        int kq0 = tid >> 6;  // 0..3
        #pragma unroll
        for (int it = 0; it < 4; it++) {
            int kq = kq0 + it * 4;  // 0..15
            float4 xv = *(const float4*)(X + (size_t)(m0 + row) * 64 + kq * 4);
            *(float4*)(&As[row][kq * 4]) = xv;
            float4 wv = *(const float4*)(W + (size_t)(n0 + row) * 64 + kq * 4);
            Bs[kq * 4 + 0][row] = wv.x;
            Bs[kq * 4 + 1][row] = wv.y;
            Bs[kq * 4 + 2][row] = wv.z;
            Bs[kq * 4 + 3][row] = wv.w;
        }
    }
    __syncthreads();

    const int tx = tid & 15, ty = tid >> 4;
    float c[4][4] = {};
    #pragma unroll
    for (int kq = 0; kq < 16; kq++) {
        float a[4][4], bb[4][4];
        #pragma unroll
        for (int i = 0; i < 4; i++) {
            float4 t = *(const float4*)(&As[ty * 4 + i][kq * 4]);
            a[i][0] = t.x; a[i][1] = t.y; a[i][2] = t.z; a[i][3] = t.w;
        }
        #pragma unroll
        for (int u = 0; u < 4; u++) {
            float4 t = *(const float4*)(&Bs[kq * 4 + u][tx * 4]);
            bb[u][0] = t.x; bb[u][1] = t.y; bb[u][2] = t.z; bb[u][3] = t.w;
        }
        #pragma unroll
        for (int i = 0; i < 4; i++)
            #pragma unroll
            for (int j = 0; j < 4; j++) {
                c[i][j] = fmaf(a[i][0], bb[0][j], c[i][j]);
                c[i][j] = fmaf(a[i][1], bb[1][j], c[i][j]);
                c[i][j] = fmaf(a[i][2], bb[2][j], c[i][j]);
                c[i][j] = fmaf(a[i][3], bb[3][j], c[i][j]);
            }
    }
    #pragma unroll
    for (int i = 0; i < 4; i++) {
        float4 o = make_float4(c[i][0], c[i][1], c[i][2], c[i][3]);
        *(float4*)(g_Y + (size_t)(m0 + ty * 4 + i) * 512 + n0 + tx * 4) = o;
    }
}

// =====================================================================
// Kernel 2: per-element setup.  Warp per element, 4 elements / 128-thr block.
// Produces S, q, Lg.
// =====================================================================
#define GS_STRIDE 68   // padded row stride for gradc to kill bank conflicts

__global__ __launch_bounds__(128) void k2_setup(
    const float* __restrict__ Xg, const float* __restrict__ Ag,
    const float* __restrict__ Bg, const float* __restrict__ ccg,
    const float* __restrict__ dcg, const float* __restrict__ adg)
{
    __shared__ float xs [4][64];
    __shared__ float zs [4][64];
    __shared__ float gsm[4][NCON * GS_STRIDE];  // gradc = Qc x + cc
    __shared__ float Bsm[4][1024];              // B tile [64][16]
    __shared__ float Lgs[4][128];               // Lg (8x16)
    __shared__ float ccs[512];

    const int tid = threadIdx.x;
    const int w = tid >> 5, lane = tid & 31;
    const int b = blockIdx.x * 4 + w;

    for (int idx = tid; idx < 512; idx += 128) ccs[idx] = ccg[idx];

    if (lane < 16)
        *(float4*)&xs[w][lane * 4] = *(const float4*)(Xg + (size_t)b * 64 + lane * 4);

    {
        const float* Bb = Bg + (size_t)b * 1024;
        #pragma unroll
        for (int it = 0; it < 8; it++) {
            int idx = it * 128 + lane * 4;
            *(float4*)&Bsm[w][idx] = *(const float4*)(Bb + idx);
        }
    }
    __syncthreads();

    // z = A x  (each lane: 2 rows)
    {
        const float* Ab = Ag + (size_t)b * 4096;
        #pragma unroll
        for (int rr = 0; rr < 2; rr++) {
            int r = lane + rr * 32;
            float acc = 0.f;
            #pragma unroll
            for (int kq = 0; kq < 16; kq++) {
                float4 a4 = *(const float4*)(Ab + r * 64 + kq * 4);
                acc = fmaf(a4.x, xs[w][kq * 4 + 0], acc);
                acc = fmaf(a4.y, xs[w][kq * 4 + 1], acc);
                acc = fmaf(a4.z, xs[w][kq * 4 + 2], acc);
                acc = fmaf(a4.w, xs[w][kq * 4 + 3], acc);
            }
            zs[w][r] = acc;
        }
    }

    // gradc = Y + cc  (store with padded stride)
    {
        const float* Yb = g_Y + (size_t)b * 512;
        #pragma unroll
        for (int it = 0; it < 4; it++) {
            int idx = it * 128 + lane * 4;
            int m = idx >> 6, i = idx & 63;
            float4 yv = *(const float4*)(Yb + idx);
            yv.x += ccs[idx + 0]; yv.y += ccs[idx + 1];
            yv.z += ccs[idx + 2]; yv.w += ccs[idx + 3];
            *(float4*)&gsm[w][m * GS_STRIDE + i] = yv;
        }
    }
    __syncwarp();

    // dots: sa = x·gradc, sb = x·cc, sc = z·gradc  per constraint
    float sa[NCON], sb[NCON], sc[NCON];
    {
        int i1 = lane, i2 = lane + 32;
        float x1 = xs[w][i1], x2 = xs[w][i2];
        float z1 = zs[w][i1], z2 = zs[w][i2];
        #pragma unroll
        for (int m = 0; m < NCON; m++) {
            float ga = gsm[w][m * GS_STRIDE + i1], gb2 = gsm[w][m * GS_STRIDE + i2];
            float ca = ccs[m * 64 + i1], cb = ccs[m * 64 + i2];
            sa[m] = fmaf(x2, gb2, x1 * ga);
            sb[m] = fmaf(x2, cb, x1 * ca);
            sc[m] = fmaf(z2, gb2, z1 * ga);
        }
    }
    #pragma unroll
    for (int off = 16; off; off >>= 1) {
        #pragma unroll
        for (int m = 0; m < NCON; m++) {
            sa[m] += __shfl_xor_sync(0xffffffffu, sa[m], off);
            sb[m] += __shfl_xor_sync(0xffffffffu, sb[m], off);
            sc[m] += __shfl_xor_sync(0xffffffffu, sc[m], off);
        }
    }

    // Lg[m][a] = -sum_i gradc[m][i] * B[i][a]   (lane: m = lane>>2, a-quad = lane&3)
    {
        int m = lane >> 2, aq = lane & 3;
        float4 acc = make_float4(0.f, 0.f, 0.f, 0.f);
        const float4* B4 = (const float4*)&Bsm[w][0];
        #pragma unroll
        for (int i = 0; i < 64; i++) {
            float gv = gsm[w][m * GS_STRIDE + i];
            float4 bv = B4[i * 4 + aq];
            acc.x = fmaf(gv, bv.x, acc.x);
            acc.y = fmaf(gv, bv.y, acc.y);
            acc.z = fmaf(gv, bv.z, acc.z);
            acc.w = fmaf(gv, bv.w, acc.w);
        }
        acc.x = -acc.x; acc.y = -acc.y; acc.z = -acc.z; acc.w = -acc.w;
        *(float4*)&Lgs[w][m * 16 + aq * 4] = acc;
        *(float4*)(g_Lg + (size_t)b * 128 + m * 16 + aq * 4) = acc;
    }
    __syncwarp();

    // q (top = bvec - Lg a_des, bottom = 0)
    if (lane < NCON) {
        int m = lane;
        float g   = 0.5f * sa[m] + 0.5f * sb[m] - dcg[m];  // g = 0.5 x·y + x·cc - dc
        float bvec = sc[m] + g;                            // = -Lf_h - h  (Lf_h=-sc, h=-g)
        float qm = bvec;
        const float* ad = adg + (size_t)b * 16;
        #pragma unroll
        for (int a = 0; a < 16; a++) qm = fmaf(-Lgs[w][m * 16 + a], ad[a], qm);
        g_q[(size_t)b * 16 + m] = qm;
        g_q[(size_t)b * 16 + 8 + m] = 0.f;
    }

    // S = 0.5 Lg Lg^T  (64 entries, 2 per lane)
    #pragma unroll
    for (int e = 0; e < 2; e++) {
        int idx = lane + e * 32;
        int r = idx >> 3, cI = idx & 7;
        float s = 0.f;
        #pragma unroll
        for (int a = 0; a < 16; a++) s = fmaf(Lgs[w][r * 16 + a], Lgs[w][cI * 16 + a], s);
        g_S[(size_t)b * 64 + idx] = 0.5f * s;
    }
}

// =====================================================================
// Kernel 3: thread per element.  Power iteration (8x8) -> lambda_max of M
// via closed form, then 250 FISTA iterations, then primal recovery.
// =====================================================================
__global__ __launch_bounds__(128) void k3_fista(const float* __restrict__ adg,
                                                float* __restrict__ out, int batch)
{
    int b = blockIdx.x * 128 + threadIdx.x;
    if (b >= batch) return;

    float S[64];
    {
        const float4* S4 = (const float4*)(g_S + (size_t)b * 64);
        #pragma unroll
        for (int i = 0; i < 16; i++) {
            float4 v = S4[i];
            S[i * 4 + 0] = v.x; S[i * 4 + 1] = v.y; S[i * 4 + 2] = v.z; S[i * 4 + 3] = v.w;
        }
    }
    float q[16];
    {
        const float4* q4 = (const float4*)(g_q + (size_t)b * 16);
        #pragma unroll
        for (int i = 0; i < 4; i++) {
            float4 v = q4[i];
            q[i * 4 + 0] = v.x; q[i * 4 + 1] = v.y; q[i * 4 + 2] = v.z; q[i * 4 + 3] = v.w;
        }
    }

    // ---- power iteration on S (8x8) ----
    float v[8];
    #pragma unroll
    for (int k = 0; k < 8; k++) v[k] = 1.0f + 0.0625f * (float)k;
    #pragma unroll 1
    for (int it = 0; it < POW_ITERS; it++) {
        float wv[8];
        #pragma unroll
        for (int k = 0; k < 8; k++) {
            float acc = 0.f;
            #pragma unroll
            for (int j = 0; j < 8; j++) acc = fmaf(S[k * 8 + j], v[j], acc);
            wv[k] = acc;
        }
        float ss = 1e-30f;
        #pragma unroll
        for (int k = 0; k < 8; k++) ss = fmaf(wv[k], wv[k], ss);
        float inv = rsqrtf(ss);
        #pragma unroll
        for (int k = 0; k < 8; k++) v[k] = wv[k] * inv;
    }
    float num = 0.f, den = 1e-30f;
    #pragma unroll
    for (int k = 0; k < 8; k++) {
        float acc = 0.f;
        #pragma unroll
        for (int j = 0; j < 8; j++) acc = fmaf(S[k * 8 + j], v[j], acc);
        num = fmaf(v[k], acc, num);
        den = fmaf(v[k], v[k], den);
    }
    float mu = fmaxf(num / den, 0.f);
    // lambda_max(M) = eps + (mu + sqrt(mu^2 + 4 eps^2)) / 2
    float lamMax = EPSC + 0.5f * (mu + sqrtf(fmaf(mu, mu, 4.f * EPSC * EPSC)));
    float L = lamMax * 1.0003f + 1e-6f;  // tiny inflation: power-iter underestimates
    float t = 1.0f / L;

    // ---- FISTA ----
    float lam[16], y[16];
    #pragma unroll
    for (int k = 0; k < 16; k++) { lam[k] = 0.f; y[k] = 0.f; }
    float tk = 1.0f;
    #pragma unroll 1
    for (int it = 0; it < N_ITERS; it++) {
        float wv[8];
        #pragma unroll
        for (int k = 0; k < 8; k++) {
            float acc = 0.f;
            #pragma unroll
            for (int j = 0; j < 8; j++) acc = fmaf(S[k * 8 + j], y[j], acc);
            wv[k] = acc;
        }
        float tk1 = 0.5f * (1.0f + sqrtf(fmaf(4.0f * tk, tk, 1.0f)));
        float beta = (tk - 1.0f) / tk1;
        #pragma unroll
        for (int k = 0; k < 8; k++) {
            float e  = EPSC * (y[k] + y[k + 8]);
            float gt = wv[k] + e - q[k];
            float gb = e - q[k + 8];
            float lt = fmaxf(fmaf(-t, gt, y[k]), 0.f);
            float lb = fmaxf(fmaf(-t, gb, y[k + 8]), 0.f);
            y[k]     = fmaf(beta, lt - lam[k], lt);
            y[k + 8] = fmaf(beta, lb - lam[k + 8], lb);
            lam[k] = lt; lam[k + 8] = lb;
        }
        tk = tk1;
    }

    // ---- primal recovery: a = a_des + 0.5 Lg^T lam_top ----
    float a[16];
    {
        const float4* ad4 = (const float4*)(adg + (size_t)b * 16);
        #pragma unroll
        for (int i = 0; i < 4; i++) {
            float4 t4 = ad4[i];
            a[i * 4 + 0] = t4.x; a[i * 4 + 1] = t4.y; a[i * 4 + 2] = t4.z; a[i * 4 + 3] = t4.w;
        }
        const float* Lgb = g_Lg + (size_t)b * 128;
        #pragma unroll
        for (int m = 0; m < 8; m++) {
            float lm = 0.5f * lam[m];
            #pragma unroll
            for (int j = 0; j < 16; j++) a[j] = fmaf(lm, Lgb[m * 16 + j], a[j]);
        }
    }
    float4* o4 = (float4*)(out + (size_t)b * 16);
    #pragma unroll
    for (int i = 0; i < 4; i++)
        o4[i] = make_float4(a[i * 4 + 0], a[i * 4 + 1], a[i * 4 + 2], a[i * 4 + 3]);
}

// =====================================================================
extern "C" void kernel_launch(void* const* d_in, const int* in_sizes, int n_in,
                              void* d_out, int out_size)
{
    const float* a_des = (const float*)d_in[0];
    const float* x     = (const float*)d_in[1];
    const float* A     = (const float*)d_in[2];
    const float* B     = (const float*)d_in[3];
    const float* Qc    = (const float*)d_in[4];
    const float* cc    = (const float*)d_in[5];
    const float* dc    = (const float*)d_in[6];
    const int batch = in_sizes[0] / ADIM;   // 16384

    dim3 g1(512 / 64, batch / 64);
    k1_gemm<<<g1, 256>>>(x, Qc);
    k2_setup<<<batch / 4, 128>>>(x, A, B, cc, dc, a_des);
    k3_fista<<<(batch + 127) / 128, 128>>>(a_des, (float*)d_out, batch);
}